// round 14
// baseline (speedup 1.0000x reference)
#include <cuda_runtime.h>
#include <cuda_fp16.h>
#include <cstdint>
#include <cstddef>

// ---------------------------------------------------------------------------
// Problem dims: y[4096,4096] = scale * x @ W^T + bias
// ---------------------------------------------------------------------------
#define TOKENS 4096
#define KDIM   4096
#define ODIM   4096

// GEMM tile config (legacy fp16 mma.sync; plain sm_103 target, no tcgen05)
#define BM 128
#define BN 128
#define BK 64
#define STAGES 3
#define KT_FULL (KDIM / BK)         // 64 k-iterations (full-K tiles)

#define A_BYTES (BM * BK * 2)       // 16384
#define B_BYTES (BN * BK * 2)       // 16384
#define STAGE_BYTES (A_BYTES + B_BYTES)      // 32768
#define SMEM_TOTAL (STAGES * STAGE_BYTES)    // 98304 per CTA (x2 resident)

#define NTHREADS 128                // 4 warps: 2(m) x 2(n), warp tile 64x64

// Hybrid split-K tail: 1024 tiles total; first NORMAL_TILES are full-K,
// the last SPLIT_TILES are split into 2 half-K CTAs each (REDG combine).
// 296 = 2 CTAs/SM x 148 SMs; 888 = 3 exactly-full waves.
#define TOTAL_TILES   1024
#define NORMAL_TILES  888
#define SPLIT_TILES   (TOTAL_TILES - NORMAL_TILES)   // 136
#define GRID_CTAS     (NORMAL_TILES + 2 * SPLIT_TILES) // 1160

// ---------------------------------------------------------------------------
// Scratch (device globals: allocation-free per harness rules)
// ---------------------------------------------------------------------------
__device__ __half g_xh[(size_t)TOKENS * KDIM];   // x rounded to fp16
__device__ __half g_w [(size_t)ODIM   * KDIM];   // ternary weights in fp16

// ---------------------------------------------------------------------------
// Helpers
// ---------------------------------------------------------------------------
__device__ __forceinline__ uint32_t smem_u32(const void* p) {
    uint32_t a;
    asm("{ .reg .u64 t; cvta.to.shared.u64 t, %1; cvt.u32.u64 %0, t; }" : "=r"(a) : "l"(p));
    return a;
}

// SW128 swizzle (Swizzle<3,4,3>): conflict-free ldmatrix on 128B rows
__device__ __forceinline__ uint32_t sw128(uint32_t off) {
    return off ^ ((off >> 3) & 0x70);
}

__device__ __forceinline__ void cp16(uint32_t dst, const void* src) {
    asm volatile("cp.async.cg.shared.global [%0], [%1], 16;" :: "r"(dst), "l"(src) : "memory");
}

__device__ __forceinline__ void ldsm4(uint32_t (&r)[4], uint32_t addr) {
    asm volatile("ldmatrix.sync.aligned.m8n8.x4.shared.b16 {%0,%1,%2,%3}, [%4];"
                 : "=r"(r[0]), "=r"(r[1]), "=r"(r[2]), "=r"(r[3]) : "r"(addr));
}

// fp16 inputs, fp32 accumulate
__device__ __forceinline__ void mma16816(float* c, const uint32_t* a, uint32_t b0, uint32_t b1) {
    asm volatile(
        "mma.sync.aligned.m16n8k16.row.col.f32.f16.f16.f32 "
        "{%0,%1,%2,%3}, {%4,%5,%6,%7}, {%8,%9}, {%0,%1,%2,%3};"
        : "+f"(c[0]), "+f"(c[1]), "+f"(c[2]), "+f"(c[3])
        : "r"(a[0]), "r"(a[1]), "r"(a[2]), "r"(a[3]), "r"(b0), "r"(b1));
}

// no-return global fp32 reduction (REDG)
__device__ __forceinline__ void red_add_f32(float* p, float v) {
    asm volatile("red.global.add.f32 [%0], %1;" :: "l"(p), "f"(v) : "memory");
}

// ---------------------------------------------------------------------------
// Fused prologue:
//   blocks [0, 8192)      : x fp32 -> fp16 (8 elems/thread)
//   blocks [8192, 16384)  : unpack masks -> fp16 W (8 elems/thread)
//   blocks [16384, 24576) : out := bias (split-tail CTAs REDG onto this;
//                           normal tiles overwrite with '=')
// ---------------------------------------------------------------------------
__global__ void __launch_bounds__(256) prologue_kernel(const float* __restrict__ x,
                                                       const int* __restrict__ pm,
                                                       const int* __restrict__ nm,
                                                       const float* __restrict__ bias,
                                                       float* __restrict__ out) {
    const int b = blockIdx.x;
    if (b < 8192) {
        size_t i = ((size_t)b * 256 + threadIdx.x) * 8;
        float4 a = *(const float4*)(x + i);
        float4 c = *(const float4*)(x + i + 4);
        float v[8] = {a.x, a.y, a.z, a.w, c.x, c.y, c.z, c.w};
        union { __half h[8]; uint4 u; } H;
#pragma unroll
        for (int k = 0; k < 8; k++) H.h[k] = __float2half_rn(v[k]);
        *(uint4*)(g_xh + i) = H.u;
    } else if (b < 16384) {
        int id = (b - 8192) * 256 + threadIdx.x;     // [0, ODIM * KDIM/8)
        int p = pm[id], n = nm[id];
        union { unsigned short h[8]; uint4 u; } W;
#pragma unroll
        for (int k = 0; k < 8; k++) {
            int pb = (p >> (7 - k)) & 1;             // MSB-first bit order
            int nb = (n >> (7 - k)) & 1;
            int t = pb - nb;                         // {-1, 0, +1}
            W.h[k] = (t == 0) ? (unsigned short)0
                              : ((t > 0) ? (unsigned short)0x3C00   // +1.0h
                                         : (unsigned short)0xBC00); // -1.0h
        }
        *(uint4*)(g_w + (size_t)id * 8) = W.u;
    } else {
        size_t i = ((size_t)(b - 16384) * 256 + threadIdx.x) * 8;
        int col = (int)(i & (ODIM - 1));             // row stride 4096 | 8
        float4 b0 = *(const float4*)(bias + col);
        float4 b1 = *(const float4*)(bias + col + 4);
        *(float4*)(out + i)     = b0;
        *(float4*)(out + i + 4) = b1;
    }
}

// ---------------------------------------------------------------------------
// Stage loader: A[128x64] + B[128x64] fp16 into SW128 smem (128 threads)
// ---------------------------------------------------------------------------
__device__ __forceinline__ void load_stage(uint32_t sbase, int m0, int n0, int kb, int tid) {
#pragma unroll
    for (int i = 0; i < 8; i++) {                // A: 1024 x 16B chunks
        int idx = tid + i * NTHREADS;
        int r = idx >> 3, c = idx & 7;
        cp16(sbase + sw128((uint32_t)(r * 128 + c * 16)),
             g_xh + (size_t)(m0 + r) * KDIM + kb + c * 8);
    }
#pragma unroll
    for (int i = 0; i < 8; i++) {                // B: 1024 x 16B chunks
        int idx = tid + i * NTHREADS;
        int r = idx >> 3, c = idx & 7;
        cp16(sbase + A_BYTES + sw128((uint32_t)(r * 128 + c * 16)),
             g_w + (size_t)(n0 + r) * KDIM + kb + c * 8);
    }
}

// ---------------------------------------------------------------------------
// Main GEMM: C[128,128] = A @ B^T, fp16 in / fp32 acc.
// 4 warps (2m x 2n), warp tile 64x64, 3-stage cp.async pipeline.
// 2 CTAs resident per SM. Hybrid split-K tail: bids >= NORMAL_TILES are
// half-K CTAs that REDG their partial onto out (pre-initialized to bias).
// ---------------------------------------------------------------------------
__global__ void __launch_bounds__(NTHREADS, 2)
ternary_gemm_kernel(const float* __restrict__ scale_p,
                    const float* __restrict__ bias,
                    float* __restrict__ out) {
    extern __shared__ char smem[];
    const uint32_t sb = smem_u32(smem);
    const int tid = threadIdx.x;
    const int lane = tid & 31, wid = tid >> 5;

    // --- tile decode: normal full-K tiles first, split half-K tail last ---
    const int bid = blockIdx.x;
    int tile, kb0, kt_cnt;
    bool is_split;
    if (bid < NORMAL_TILES) {
        tile = bid; kb0 = 0; kt_cnt = KT_FULL; is_split = false;
    } else {
        const int sid = bid - NORMAL_TILES;          // [0, 2*SPLIT_TILES)
        const int half = sid / SPLIT_TILES;          // 0 or 1
        tile = NORMAL_TILES + (sid - half * SPLIT_TILES);
        kb0 = half * (KDIM / 2);
        kt_cnt = KT_FULL / 2;
        is_split = true;
    }
    const int m0 = (tile >> 5) * BM;                 // tile/32
    const int n0 = (tile & 31) * BN;                 // tile%32

    const int wm = (wid & 1) * 64;        // 2 m-warps
    const int wn = (wid >> 1) * 64;       // 2 n-warps
    const int mat = lane >> 3, lr = lane & 7;

    // Precomputed swizzled byte offsets (within A region / B region)
    uint32_t swA[4], swB[4];
#pragma unroll
    for (int mt = 0; mt < 4; mt++) {
        int row = wm + mt * 16 + ((mat & 1) << 3) + lr;
        swA[mt] = sw128((uint32_t)(row * 128 + ((mat >> 1) << 4)));
    }
#pragma unroll
    for (int nt = 0; nt < 4; nt++) {
        int row = wn + nt * 16 + ((mat >> 1) << 3) + lr;
        swB[nt] = sw128((uint32_t)(row * 128 + ((mat & 1) << 4)));
    }

    // fp32 accumulators: [mt][n8][4] = 128 regs
    float acc[4][8][4];
#pragma unroll
    for (int i = 0; i < 4; i++)
#pragma unroll
        for (int j = 0; j < 8; j++)
#pragma unroll
            for (int c = 0; c < 4; c++) acc[i][j][c] = 0.0f;

    // ---- pipeline prologue: fill STAGES-1 = 2 stages ----
#pragma unroll
    for (int s = 0; s < STAGES - 1; s++) {
        load_stage(sb + s * STAGE_BYTES, m0, n0, kb0 + s * BK, tid);
        asm volatile("cp.async.commit_group;" ::: "memory");
    }
    asm volatile("cp.async.wait_group %0;" :: "n"(STAGES - 2) : "memory");
    __syncthreads();

    int rs = 0, ws = STAGES - 1;

    for (int k = 0; k < kt_cnt; k++) {
        // prefetch stage k+STAGES-1
        if (k + STAGES - 1 < kt_cnt)
            load_stage(sb + ws * STAGE_BYTES, m0, n0, kb0 + (k + STAGES - 1) * BK, tid);
        asm volatile("cp.async.commit_group;" ::: "memory");

        const uint32_t abase = sb + rs * STAGE_BYTES;
        const uint32_t bbase = abase + A_BYTES;

#pragma unroll
        for (int kt = 0; kt < 4; kt++) {
            const uint32_t ktx = (uint32_t)(kt << 5);
            uint32_t Af[4][4], Bf[4][4];
#pragma unroll
            for (int mt = 0; mt < 4; mt++) ldsm4(Af[mt], abase + (swA[mt] ^ ktx));
#pragma unroll
            for (int nt = 0; nt < 4; nt++) ldsm4(Bf[nt], bbase + (swB[nt] ^ ktx));
#pragma unroll
            for (int mt = 0; mt < 4; mt++) {
#pragma unroll
                for (int nt = 0; nt < 4; nt++) {
                    mma16816(acc[mt][nt * 2],     Af[mt], Bf[nt][0], Bf[nt][1]);
                    mma16816(acc[mt][nt * 2 + 1], Af[mt], Bf[nt][2], Bf[nt][3]);
                }
            }
        }

        ws = rs;
        rs = (rs + 1) % STAGES;
        asm volatile("cp.async.wait_group %0;" :: "n"(STAGES - 2) : "memory");
        __syncthreads();
    }

    // ---- epilogue ----
    const float scale = __ldg(scale_p);
    if (!is_split) {
        // normal tile: y = scale * acc + bias, direct float2 stores
#pragma unroll
        for (int mt = 0; mt < 4; mt++) {
            const int row = m0 + wm + mt * 16 + (lane >> 2);
#pragma unroll
            for (int n8 = 0; n8 < 8; n8++) {
                const int col = n0 + wn + n8 * 8 + (lane & 3) * 2;
                const float2 bb = *(const float2*)(bias + col);
                float2 v0, v1;
                v0.x = fmaf(scale, acc[mt][n8][0], bb.x);
                v0.y = fmaf(scale, acc[mt][n8][1], bb.y);
                v1.x = fmaf(scale, acc[mt][n8][2], bb.x);
                v1.y = fmaf(scale, acc[mt][n8][3], bb.y);
                *(float2*)(out + (size_t)row * ODIM + col)       = v0;
                *(float2*)(out + (size_t)(row + 8) * ODIM + col) = v1;
            }
        }
    } else {
        // split tile: REDG partial onto out (pre-initialized to bias)
#pragma unroll
        for (int mt = 0; mt < 4; mt++) {
            const int row = m0 + wm + mt * 16 + (lane >> 2);
#pragma unroll
            for (int n8 = 0; n8 < 8; n8++) {
                const int col = n0 + wn + n8 * 8 + (lane & 3) * 2;
                float* p0 = out + (size_t)row * ODIM + col;
                float* p1 = out + (size_t)(row + 8) * ODIM + col;
                red_add_f32(p0,     scale * acc[mt][n8][0]);
                red_add_f32(p0 + 1, scale * acc[mt][n8][1]);
                red_add_f32(p1,     scale * acc[mt][n8][2]);
                red_add_f32(p1 + 1, scale * acc[mt][n8][3]);
            }
        }
    }
}

// ---------------------------------------------------------------------------
// Launch
// ---------------------------------------------------------------------------
extern "C" void kernel_launch(void* const* d_in, const int* in_sizes, int n_in,
                              void* d_out, int out_size) {
    const float* x     = (const float*)d_in[0];
    const int*   pm    = (const int*)d_in[1];
    const int*   nm    = (const int*)d_in[2];
    const float* scale = (const float*)d_in[3];
    const float* bias  = (const float*)d_in[4];
    float* out = (float*)d_out;

    (void)in_sizes; (void)n_in; (void)out_size;

    // fused prologue: x->fp16, mask unpack, out := bias
    prologue_kernel<<<24576, 256>>>(x, pm, nm, bias, out);

    cudaFuncSetAttribute(ternary_gemm_kernel,
                         cudaFuncAttributeMaxDynamicSharedMemorySize, SMEM_TOTAL);
    ternary_gemm_kernel<<<GRID_CTAS, NTHREADS, SMEM_TOTAL>>>(scale, bias, out);
}

// round 15
// speedup vs baseline: 1.0421x; 1.0421x over previous
#include <cuda_runtime.h>
#include <cuda_fp16.h>
#include <cstdint>
#include <cstddef>

// ---------------------------------------------------------------------------
// Problem dims: y[4096,4096] = scale * x @ W^T + bias
// ---------------------------------------------------------------------------
#define TOKENS 4096
#define KDIM   4096
#define ODIM   4096

// GEMM tile config (legacy fp16 mma.sync; plain sm_103 target, no tcgen05)
#define BM 128
#define BN 128
#define BK 64
#define STAGES 3
#define KT_FULL (KDIM / BK)         // 64 k-iterations (full-K tiles)

#define A_BYTES (BM * BK * 2)       // 16384
#define B_BYTES (BN * BK * 2)       // 16384
#define STAGE_BYTES (A_BYTES + B_BYTES)      // 32768
#define SMEM_TOTAL (STAGES * STAGE_BYTES)    // 98304 per CTA (x2 resident)

#define NTHREADS 128                // 4 warps: 2(m) x 2(n), warp tile 64x64

// Hybrid split-K tail: 1024 tiles total; first NORMAL_TILES are full-K,
// the last SPLIT_TILES are split into 2 half-K CTAs each (REDG combine).
// 296 = 2 CTAs/SM x 148 SMs; 888 = 3 exactly-full waves.
#define TOTAL_TILES   1024
#define NORMAL_TILES  888
#define SPLIT_TILES   (TOTAL_TILES - NORMAL_TILES)   // 136
#define GRID_CTAS     (NORMAL_TILES + 2 * SPLIT_TILES) // 1160

// prologue block ranges
#define PRO_X_BLOCKS    8192
#define PRO_W_BLOCKS    8192
#define PRO_INIT_BLOCKS ((SPLIT_TILES * BM * BN) / (256 * 8))  // 1088
#define PRO_TOTAL_BLOCKS (PRO_X_BLOCKS + PRO_W_BLOCKS + PRO_INIT_BLOCKS)

// ---------------------------------------------------------------------------
// Scratch (device globals: allocation-free per harness rules)
// ---------------------------------------------------------------------------
__device__ __half g_xh[(size_t)TOKENS * KDIM];   // x rounded to fp16
__device__ __half g_w [(size_t)ODIM   * KDIM];   // ternary weights in fp16

// ---------------------------------------------------------------------------
// Helpers
// ---------------------------------------------------------------------------
__device__ __forceinline__ uint32_t smem_u32(const void* p) {
    uint32_t a;
    asm("{ .reg .u64 t; cvta.to.shared.u64 t, %1; cvt.u32.u64 %0, t; }" : "=r"(a) : "l"(p));
    return a;
}

// SW128 swizzle (Swizzle<3,4,3>): conflict-free ldmatrix on 128B rows
__device__ __forceinline__ uint32_t sw128(uint32_t off) {
    return off ^ ((off >> 3) & 0x70);
}

__device__ __forceinline__ void cp16(uint32_t dst, const void* src) {
    asm volatile("cp.async.cg.shared.global [%0], [%1], 16;" :: "r"(dst), "l"(src) : "memory");
}

__device__ __forceinline__ void ldsm4(uint32_t (&r)[4], uint32_t addr) {
    asm volatile("ldmatrix.sync.aligned.m8n8.x4.shared.b16 {%0,%1,%2,%3}, [%4];"
                 : "=r"(r[0]), "=r"(r[1]), "=r"(r[2]), "=r"(r[3]) : "r"(addr));
}

// fp16 inputs, fp32 accumulate
__device__ __forceinline__ void mma16816(float* c, const uint32_t* a, uint32_t b0, uint32_t b1) {
    asm volatile(
        "mma.sync.aligned.m16n8k16.row.col.f32.f16.f16.f32 "
        "{%0,%1,%2,%3}, {%4,%5,%6,%7}, {%8,%9}, {%0,%1,%2,%3};"
        : "+f"(c[0]), "+f"(c[1]), "+f"(c[2]), "+f"(c[3])
        : "r"(a[0]), "r"(a[1]), "r"(a[2]), "r"(a[3]), "r"(b0), "r"(b1));
}

// no-return global fp32 reduction (REDG)
__device__ __forceinline__ void red_add_f32(float* p, float v) {
    asm volatile("red.global.add.f32 [%0], %1;" :: "l"(p), "f"(v) : "memory");
}

// ---------------------------------------------------------------------------
// Fused prologue:
//   blocks [0, 8192)          : x fp32 -> fp16 (8 elems/thread)
//   blocks [8192, 16384)      : unpack masks -> fp16 W (8 elems/thread)
//   blocks [16384, 16384+1088): out := bias, ONLY over the 136 split tiles
//                               (normal tiles overwrite with '=')
// ---------------------------------------------------------------------------
__global__ void __launch_bounds__(256) prologue_kernel(const float* __restrict__ x,
                                                       const int* __restrict__ pm,
                                                       const int* __restrict__ nm,
                                                       const float* __restrict__ bias,
                                                       float* __restrict__ out) {
    const int b = blockIdx.x;
    if (b < PRO_X_BLOCKS) {
        size_t i = ((size_t)b * 256 + threadIdx.x) * 8;
        float4 a = *(const float4*)(x + i);
        float4 c = *(const float4*)(x + i + 4);
        float v[8] = {a.x, a.y, a.z, a.w, c.x, c.y, c.z, c.w};
        union { __half h[8]; uint4 u; } H;
#pragma unroll
        for (int k = 0; k < 8; k++) H.h[k] = __float2half_rn(v[k]);
        *(uint4*)(g_xh + i) = H.u;
    } else if (b < PRO_X_BLOCKS + PRO_W_BLOCKS) {
        int id = (b - PRO_X_BLOCKS) * 256 + threadIdx.x;   // [0, ODIM * KDIM/8)
        int p = pm[id], n = nm[id];
        union { unsigned short h[8]; uint4 u; } W;
#pragma unroll
        for (int k = 0; k < 8; k++) {
            int pb = (p >> (7 - k)) & 1;             // MSB-first bit order
            int nb = (n >> (7 - k)) & 1;
            int t = pb - nb;                         // {-1, 0, +1}
            W.h[k] = (t == 0) ? (unsigned short)0
                              : ((t > 0) ? (unsigned short)0x3C00   // +1.0h
                                         : (unsigned short)0xBC00); // -1.0h
        }
        *(uint4*)(g_w + (size_t)id * 8) = W.u;
    } else {
        // bias-init restricted to split tiles [NORMAL_TILES, TOTAL_TILES)
        int i = ((b - PRO_X_BLOCKS - PRO_W_BLOCKS) * 256 + threadIdx.x) * 8;
        const int tile = NORMAL_TILES + (i >> 14);   // /16384 elems per tile
        const int off  = i & 16383;
        const int row  = (tile >> 5) * BM + (off >> 7);
        const int col  = (tile & 31) * BN + (off & 127);
        float4 b0 = *(const float4*)(bias + col);
        float4 b1 = *(const float4*)(bias + col + 4);
        float* dst = out + (size_t)row * ODIM + col;
        *(float4*)(dst)     = b0;
        *(float4*)(dst + 4) = b1;
    }
}

// ---------------------------------------------------------------------------
// Stage loader: A[128x64] + B[128x64] fp16 into SW128 smem (128 threads)
// ---------------------------------------------------------------------------
__device__ __forceinline__ void load_stage(uint32_t sbase, int m0, int n0, int kb, int tid) {
#pragma unroll
    for (int i = 0; i < 8; i++) {                // A: 1024 x 16B chunks
        int idx = tid + i * NTHREADS;
        int r = idx >> 3, c = idx & 7;
        cp16(sbase + sw128((uint32_t)(r * 128 + c * 16)),
             g_xh + (size_t)(m0 + r) * KDIM + kb + c * 8);
    }
#pragma unroll
    for (int i = 0; i < 8; i++) {                // B: 1024 x 16B chunks
        int idx = tid + i * NTHREADS;
        int r = idx >> 3, c = idx & 7;
        cp16(sbase + A_BYTES + sw128((uint32_t)(r * 128 + c * 16)),
             g_w + (size_t)(n0 + r) * KDIM + kb + c * 8);
    }
}

// ---------------------------------------------------------------------------
// Main GEMM: C[128,128] = A @ B^T, fp16 in / fp32 acc.
// 4 warps (2m x 2n), warp tile 64x64, 3-stage cp.async pipeline.
// 2 CTAs resident per SM. Hybrid split-K tail: bids >= NORMAL_TILES are
// half-K CTAs that REDG their partial onto out (pre-initialized to bias).
// ---------------------------------------------------------------------------
__global__ void __launch_bounds__(NTHREADS, 2)
ternary_gemm_kernel(const float* __restrict__ scale_p,
                    const float* __restrict__ bias,
                    float* __restrict__ out) {
    extern __shared__ char smem[];
    const uint32_t sb = smem_u32(smem);
    const int tid = threadIdx.x;
    const int lane = tid & 31, wid = tid >> 5;

    // --- tile decode: normal full-K tiles first, split half-K tail last ---
    const int bid = blockIdx.x;
    int tile, kb0, kt_cnt;
    bool is_split;
    if (bid < NORMAL_TILES) {
        tile = bid; kb0 = 0; kt_cnt = KT_FULL; is_split = false;
    } else {
        const int sid = bid - NORMAL_TILES;          // [0, 2*SPLIT_TILES)
        const int half = sid / SPLIT_TILES;          // 0 or 1
        tile = NORMAL_TILES + (sid - half * SPLIT_TILES);
        kb0 = half * (KDIM / 2);
        kt_cnt = KT_FULL / 2;
        is_split = true;
    }
    const int m0 = (tile >> 5) * BM;                 // tile/32
    const int n0 = (tile & 31) * BN;                 // tile%32

    const int wm = (wid & 1) * 64;        // 2 m-warps
    const int wn = (wid >> 1) * 64;       // 2 n-warps
    const int mat = lane >> 3, lr = lane & 7;

    // Precomputed swizzled byte offsets (within A region / B region)
    uint32_t swA[4], swB[4];
#pragma unroll
    for (int mt = 0; mt < 4; mt++) {
        int row = wm + mt * 16 + ((mat & 1) << 3) + lr;
        swA[mt] = sw128((uint32_t)(row * 128 + ((mat >> 1) << 4)));
    }
#pragma unroll
    for (int nt = 0; nt < 4; nt++) {
        int row = wn + nt * 16 + ((mat >> 1) << 3) + lr;
        swB[nt] = sw128((uint32_t)(row * 128 + ((mat & 1) << 4)));
    }

    // fp32 accumulators: [mt][n8][4] = 128 regs
    float acc[4][8][4];
#pragma unroll
    for (int i = 0; i < 4; i++)
#pragma unroll
        for (int j = 0; j < 8; j++)
#pragma unroll
            for (int c = 0; c < 4; c++) acc[i][j][c] = 0.0f;

    // ---- pipeline prologue: fill STAGES-1 = 2 stages ----
#pragma unroll
    for (int s = 0; s < STAGES - 1; s++) {
        load_stage(sb + s * STAGE_BYTES, m0, n0, kb0 + s * BK, tid);
        asm volatile("cp.async.commit_group;" ::: "memory");
    }
    asm volatile("cp.async.wait_group %0;" :: "n"(STAGES - 2) : "memory");
    __syncthreads();

    int rs = 0, ws = STAGES - 1;

    for (int k = 0; k < kt_cnt; k++) {
        // prefetch stage k+STAGES-1
        if (k + STAGES - 1 < kt_cnt)
            load_stage(sb + ws * STAGE_BYTES, m0, n0, kb0 + (k + STAGES - 1) * BK, tid);
        asm volatile("cp.async.commit_group;" ::: "memory");

        const uint32_t abase = sb + rs * STAGE_BYTES;
        const uint32_t bbase = abase + A_BYTES;

#pragma unroll
        for (int kt = 0; kt < 4; kt++) {
            const uint32_t ktx = (uint32_t)(kt << 5);
            uint32_t Af[4][4], Bf[4][4];
#pragma unroll
            for (int mt = 0; mt < 4; mt++) ldsm4(Af[mt], abase + (swA[mt] ^ ktx));
#pragma unroll
            for (int nt = 0; nt < 4; nt++) ldsm4(Bf[nt], bbase + (swB[nt] ^ ktx));
#pragma unroll
            for (int mt = 0; mt < 4; mt++) {
#pragma unroll
                for (int nt = 0; nt < 4; nt++) {
                    mma16816(acc[mt][nt * 2],     Af[mt], Bf[nt][0], Bf[nt][1]);
                    mma16816(acc[mt][nt * 2 + 1], Af[mt], Bf[nt][2], Bf[nt][3]);
                }
            }
        }

        ws = rs;
        rs = (rs + 1) % STAGES;
        asm volatile("cp.async.wait_group %0;" :: "n"(STAGES - 2) : "memory");
        __syncthreads();
    }

    // ---- epilogue ----
    const float scale = __ldg(scale_p);
    if (!is_split) {
        // normal tile: y = scale * acc + bias, direct float2 stores
#pragma unroll
        for (int mt = 0; mt < 4; mt++) {
            const int row = m0 + wm + mt * 16 + (lane >> 2);
#pragma unroll
            for (int n8 = 0; n8 < 8; n8++) {
                const int col = n0 + wn + n8 * 8 + (lane & 3) * 2;
                const float2 bb = *(const float2*)(bias + col);
                float2 v0, v1;
                v0.x = fmaf(scale, acc[mt][n8][0], bb.x);
                v0.y = fmaf(scale, acc[mt][n8][1], bb.y);
                v1.x = fmaf(scale, acc[mt][n8][2], bb.x);
                v1.y = fmaf(scale, acc[mt][n8][3], bb.y);
                *(float2*)(out + (size_t)row * ODIM + col)       = v0;
                *(float2*)(out + (size_t)(row + 8) * ODIM + col) = v1;
            }
        }
    } else {
        // split tile: REDG partial onto out (pre-initialized to bias)
#pragma unroll
        for (int mt = 0; mt < 4; mt++) {
            const int row = m0 + wm + mt * 16 + (lane >> 2);
#pragma unroll
            for (int n8 = 0; n8 < 8; n8++) {
                const int col = n0 + wn + n8 * 8 + (lane & 3) * 2;
                float* p0 = out + (size_t)row * ODIM + col;
                float* p1 = out + (size_t)(row + 8) * ODIM + col;
                red_add_f32(p0,     scale * acc[mt][n8][0]);
                red_add_f32(p0 + 1, scale * acc[mt][n8][1]);
                red_add_f32(p1,     scale * acc[mt][n8][2]);
                red_add_f32(p1 + 1, scale * acc[mt][n8][3]);
            }
        }
    }
}

// ---------------------------------------------------------------------------
// Launch
// ---------------------------------------------------------------------------
extern "C" void kernel_launch(void* const* d_in, const int* in_sizes, int n_in,
                              void* d_out, int out_size) {
    const float* x     = (const float*)d_in[0];
    const int*   pm    = (const int*)d_in[1];
    const int*   nm    = (const int*)d_in[2];
    const float* scale = (const float*)d_in[3];
    const float* bias  = (const float*)d_in[4];
    float* out = (float*)d_out;

    (void)in_sizes; (void)n_in; (void)out_size;

    // fused prologue: x->fp16, mask unpack, out := bias (split region only)
    prologue_kernel<<<PRO_TOTAL_BLOCKS, 256>>>(x, pm, nm, bias, out);

    cudaFuncSetAttribute(ternary_gemm_kernel,
                         cudaFuncAttributeMaxDynamicSharedMemorySize, SMEM_TOTAL);
    ternary_gemm_kernel<<<GRID_CTAS, NTHREADS, SMEM_TOTAL>>>(scale, bias, out);
}